// round 1
// baseline (speedup 1.0000x reference)
#include <cuda_runtime.h>
#include <cstdint>

// ---------------------------------------------------------------------------
// Upsample_18279380811797
// out = stack_k( x @ W[k] )  [8*65536, 128]  -> BN(train stats) -> ReLU
// Phase 1: tiled fp32 GEMM (128x128x16 block, 8x8 microtile), writes pre-BN
//          result to d_out and deterministic per-block column sum/sumsq
//          partials to __device__ scratch.
// Phase 2: reduce partials -> per-channel scale/bias.
// Phase 3: in-place y = max(v*scale[d]+bias[d], 0).
// ---------------------------------------------------------------------------

#define M_TOTAL   65536
#define K_TOTAL   256
#define COUT      128
#define NOFFS     8
#define BM        128
#define BN        128
#define BK        16
#define MTILES    (M_TOTAL / BM)          // 512
#define NBLOCKS   (MTILES * NOFFS)        // 4096

__device__ float g_psum[NBLOCKS * COUT];  // per-block column sums
__device__ float g_psq [NBLOCKS * COUT];  // per-block column sumsq
__device__ float g_scale[COUT];
__device__ float g_bias [COUT];

__global__ __launch_bounds__(256) void gemm_stats_kernel(
    const float* __restrict__ x,   // [65536, 256]
    const float* __restrict__ W,   // [8, 256, 128]
    float* __restrict__ out)       // [8*65536, 128]
{
    __shared__ union {
        struct { float As[BK][BM]; float Bs[BK][BN]; } t;   // 16 KB
        float red[2][16][COUT];                             // 16 KB
    } sm;

    const int bx = blockIdx.x;        // M tile (0..511)
    const int kt = blockIdx.y;        // offset k (0..7)
    const int tid = threadIdx.x;
    const int tr = tid >> 4;          // 0..15 row group
    const int tc = tid & 15;          // 0..15 col group

    const float* A = x + (size_t)bx * BM * K_TOTAL;
    const float* B = W + (size_t)kt * K_TOTAL * COUT;

    float acc[8][8];
    #pragma unroll
    for (int i = 0; i < 8; i++)
        #pragma unroll
        for (int j = 0; j < 8; j++) acc[i][j] = 0.f;

    for (int k0 = 0; k0 < K_TOTAL; k0 += BK) {
        // Load A tile [BM x BK] -> As[k][m] (transposed for compute)
        #pragma unroll
        for (int l = 0; l < 2; l++) {
            int idx = tid + 256 * l;          // 0..511 float4 slots
            int m  = idx >> 2;                // 0..127
            int kv = idx & 3;                 // which float4 along k
            float4 v = *(const float4*)(A + (size_t)m * K_TOTAL + k0 + kv * 4);
            sm.t.As[kv * 4 + 0][m] = v.x;
            sm.t.As[kv * 4 + 1][m] = v.y;
            sm.t.As[kv * 4 + 2][m] = v.z;
            sm.t.As[kv * 4 + 3][m] = v.w;
        }
        // Load B tile [BK x BN] (row-major, contiguous along d)
        #pragma unroll
        for (int l = 0; l < 2; l++) {
            int idx = tid + 256 * l;
            int kk = idx >> 5;                // 0..15
            int dv = idx & 31;                // float4 along d
            *(float4*)&sm.t.Bs[kk][dv * 4] =
                *(const float4*)(B + (size_t)(k0 + kk) * COUT + dv * 4);
        }
        __syncthreads();

        #pragma unroll
        for (int kk = 0; kk < BK; kk++) {
            float ra[8], rb[8];
            *(float4*)&ra[0] = *(float4*)&sm.t.As[kk][tr * 8];
            *(float4*)&ra[4] = *(float4*)&sm.t.As[kk][tr * 8 + 4];
            *(float4*)&rb[0] = *(float4*)&sm.t.Bs[kk][tc * 8];
            *(float4*)&rb[4] = *(float4*)&sm.t.Bs[kk][tc * 8 + 4];
            #pragma unroll
            for (int i = 0; i < 8; i++)
                #pragma unroll
                for (int j = 0; j < 8; j++)
                    acc[i][j] = fmaf(ra[i], rb[j], acc[i][j]);
        }
        __syncthreads();
    }

    // Epilogue: store pre-BN result + per-thread column partial sums
    float csum[8], csq[8];
    #pragma unroll
    for (int j = 0; j < 8; j++) { csum[j] = 0.f; csq[j] = 0.f; }

    const size_t row0 = (size_t)kt * M_TOTAL + (size_t)bx * BM + tr * 8;
    #pragma unroll
    for (int i = 0; i < 8; i++) {
        float* orow = out + (row0 + i) * COUT + tc * 8;
        *(float4*)&orow[0] = *(float4*)&acc[i][0];
        *(float4*)&orow[4] = *(float4*)&acc[i][4];
        #pragma unroll
        for (int j = 0; j < 8; j++) {
            float v = acc[i][j];
            csum[j] += v;
            csq[j]  += v * v;
        }
    }

    // Deterministic block reduction over tr (16 row-groups) per channel
    #pragma unroll
    for (int j = 0; j < 8; j++) {
        sm.red[0][tr][tc * 8 + j] = csum[j];
        sm.red[1][tr][tc * 8 + j] = csq[j];
    }
    __syncthreads();
    if (tid < COUT) {
        float s = 0.f, q = 0.f;
        #pragma unroll
        for (int r = 0; r < 16; r++) {
            s += sm.red[0][r][tid];
            q += sm.red[1][r][tid];
        }
        const int blin = kt * MTILES + bx;
        g_psum[(size_t)blin * COUT + tid] = s;
        g_psq [(size_t)blin * COUT + tid] = q;
    }
}

__global__ __launch_bounds__(256) void stats_kernel(
    const float* __restrict__ gamma, const float* __restrict__ beta)
{
    const int d = blockIdx.x;          // 0..127 (one block per channel)
    __shared__ float ss[256], sq[256];
    float s = 0.f, q = 0.f;
    for (int i = threadIdx.x; i < NBLOCKS; i += 256) {
        s += g_psum[(size_t)i * COUT + d];
        q += g_psq [(size_t)i * COUT + d];
    }
    ss[threadIdx.x] = s; sq[threadIdx.x] = q;
    __syncthreads();
    for (int stride = 128; stride > 0; stride >>= 1) {
        if (threadIdx.x < stride) {
            ss[threadIdx.x] += ss[threadIdx.x + stride];
            sq[threadIdx.x] += sq[threadIdx.x + stride];
        }
        __syncthreads();
    }
    if (threadIdx.x == 0) {
        const float inv = 1.f / (float)((size_t)NOFFS * M_TOTAL);
        float mean = ss[0] * inv;
        float var  = sq[0] * inv - mean * mean;
        float sc   = gamma[d] * rsqrtf(var + 1e-5f);
        g_scale[d] = sc;
        g_bias[d]  = beta[d] - mean * sc;
    }
}

__global__ __launch_bounds__(256) void bn_relu_kernel(float* __restrict__ out)
{
    __shared__ float sc[COUT], bi[COUT];
    if (threadIdx.x < COUT) {
        sc[threadIdx.x] = g_scale[threadIdx.x];
        bi[threadIdx.x] = g_bias[threadIdx.x];
    }
    __syncthreads();
    const size_t idx = (size_t)blockIdx.x * blockDim.x + threadIdx.x; // float4 index
    const int d0 = (int)((idx * 4) & (COUT - 1));
    float4 v = ((float4*)out)[idx];
    v.x = fmaxf(fmaf(v.x, sc[d0 + 0], bi[d0 + 0]), 0.f);
    v.y = fmaxf(fmaf(v.y, sc[d0 + 1], bi[d0 + 1]), 0.f);
    v.z = fmaxf(fmaf(v.z, sc[d0 + 2], bi[d0 + 2]), 0.f);
    v.w = fmaxf(fmaf(v.w, sc[d0 + 3], bi[d0 + 3]), 0.f);
    ((float4*)out)[idx] = v;
}

extern "C" void kernel_launch(void* const* d_in, const int* in_sizes, int n_in,
                              void* d_out, int out_size)
{
    const float* x     = (const float*)d_in[0];   // [65536, 256]
    const float* W     = (const float*)d_in[1];   // [8, 256, 128]
    const float* gamma = (const float*)d_in[2];   // [128]
    const float* beta  = (const float*)d_in[3];   // [128]
    float* out = (float*)d_out;                   // [8*65536, 128]

    dim3 ggrid(MTILES, NOFFS);
    gemm_stats_kernel<<<ggrid, 256>>>(x, W, out);
    stats_kernel<<<COUT, 256>>>(gamma, beta);
    const size_t n4 = (size_t)NOFFS * M_TOTAL * COUT / 4;  // 16,777,216
    bn_relu_kernel<<<(unsigned)(n4 / 256), 256>>>(out);
}

// round 3
// speedup vs baseline: 1.7189x; 1.7189x over previous
#include <cuda_runtime.h>
#include <cuda_bf16.h>
#include <cstdint>

// ============================================================================
// Upsample: out = stack_k(x @ W[k]) [8*65536,128] -> BN(train stats) -> ReLU
// Tensor-core path via baseline PTX mma.sync (compute_103 has no tcgen05).
// Split-precision bf16: D = Ah*Bh + Ah*Bl + Al*Bh, fp32 accumulate.
// ============================================================================

#define MT      65536
#define KT      256
#define CO      128
#define NOFF    8
#define BM      128
#define MTILES  512

// ---- device scratch ----
__device__ __align__(16) __nv_bfloat16 g_xh[(size_t)MT * KT];
__device__ __align__(16) __nv_bfloat16 g_xl[(size_t)MT * KT];
__device__ __align__(16) __nv_bfloat16 g_wh[NOFF * CO * KT];  // [k][n][kk] (k-contig)
__device__ __align__(16) __nv_bfloat16 g_wl[NOFF * CO * KT];
__device__ float g_psum[MTILES * CO];
__device__ float g_psq [MTILES * CO];
__device__ float g_scale[CO];
__device__ float g_bias [CO];

// ---- SMEM layout (bytes) ----
// A: 2 terms x [128 rows x 264 bf16] (stride 528B -> conflict-free ldmatrix)
#define A_TERM_B   67584                 // 128*264*2
#define O_A        0
// B: 2 stages x 2 terms x [128 n x 72 bf16] (stride 144B)
#define B_TERM_B   18432                 // 128*72*2
#define B_STAGE_B  36864
#define O_B        (2 * A_TERM_B)        // 135168
#define O_ST       (O_B + 2 * B_STAGE_B) // 208896
#define SMEM_BYTES (O_ST + 1024 * 4)     // + accS[512]/accQ[512] = 212992

// ---- PTX helpers ----
__device__ __forceinline__ uint32_t smem_u32(const void* p) {
    uint32_t a;
    asm("{ .reg .u64 t; cvta.to.shared.u64 t, %1; cvt.u32.u64 %0, t; }" : "=r"(a) : "l"(p));
    return a;
}
__device__ __forceinline__ void cp16(uint32_t dst, const void* src) {
    asm volatile("cp.async.cg.shared.global [%0], [%1], 16;" :: "r"(dst), "l"(src) : "memory");
}
#define CP_COMMIT() asm volatile("cp.async.commit_group;" ::: "memory")
#define CP_WAIT(n)  asm volatile("cp.async.wait_group %0;" :: "n"(n) : "memory")

__device__ __forceinline__ void ldsm4(uint32_t r[4], uint32_t a) {
    asm volatile("ldmatrix.sync.aligned.m8n8.x4.shared.b16 {%0,%1,%2,%3}, [%4];"
                 : "=r"(r[0]), "=r"(r[1]), "=r"(r[2]), "=r"(r[3]) : "r"(a));
}
__device__ __forceinline__ void mma16816(float d[4], const uint32_t a[4], const uint32_t b[2]) {
    asm volatile(
        "mma.sync.aligned.m16n8k16.row.col.f32.bf16.bf16.f32 "
        "{%0,%1,%2,%3}, {%4,%5,%6,%7}, {%8,%9}, {%0,%1,%2,%3};"
        : "+f"(d[0]), "+f"(d[1]), "+f"(d[2]), "+f"(d[3])
        : "r"(a[0]), "r"(a[1]), "r"(a[2]), "r"(a[3]), "r"(b[0]), "r"(b[1]));
}

// ============================================================================
// prep: fp32 -> bf16 hi/lo splits
// ============================================================================
__global__ __launch_bounds__(256) void convert_x(const float* __restrict__ x) {
    size_t i = ((size_t)blockIdx.x * 256 + threadIdx.x) * 8;
    float4 a = *(const float4*)(x + i);
    float4 b = *(const float4*)(x + i + 4);
    float v[8] = {a.x, a.y, a.z, a.w, b.x, b.y, b.z, b.w};
    __nv_bfloat16 h[8], l[8];
#pragma unroll
    for (int j = 0; j < 8; j++) {
        h[j] = __float2bfloat16(v[j]);
        l[j] = __float2bfloat16(v[j] - __bfloat162float(h[j]));
    }
    *(uint4*)(g_xh + i) = *(uint4*)h;
    *(uint4*)(g_xl + i) = *(uint4*)l;
}

__global__ __launch_bounds__(256) void convert_w(const float* __restrict__ W) {
    int b = blockIdx.x;              // k*128 + n
    int k = b >> 7, n = b & 127;
    int kk = threadIdx.x;            // 0..255
    float v = W[((size_t)(k * KT + kk)) * CO + n];
    __nv_bfloat16 h = __float2bfloat16(v);
    g_wh[(size_t)b * KT + kk] = h;
    g_wl[(size_t)b * KT + kk] = __float2bfloat16(v - __bfloat162float(h));
}

// ============================================================================
// main GEMM: 512 CTAs (one 128-row M tile), loop 8 offsets, mma.sync bf16 x3
// ============================================================================
__global__ __launch_bounds__(256, 1) void gemm_mma(float* __restrict__ out)
{
    extern __shared__ char smem[];
    const uint32_t sb = smem_u32(smem);
    const int tid = threadIdx.x, lane = tid & 31, w = tid >> 5;
    const int wm = w & 3, wn = w >> 2;          // 4 x 2 warp grid
    const int bx = blockIdx.x;

    float* accS = (float*)(smem + O_ST);        // [4][128]
    float* accQ = accS + 512;
    for (int i = tid; i < 1024; i += 256) accS[i] = 0.f;

    // A tile (both terms) via cp.async: 2*128 rows * 32 kblk16
    {
        const __nv_bfloat16* base0 = g_xh + (size_t)bx * BM * KT;
        const __nv_bfloat16* base1 = g_xl + (size_t)bx * BM * KT;
        for (int i = tid; i < 8192; i += 256) {
            int term = i >> 12, rem = i & 4095, m = rem >> 5, kb = rem & 31;
            const __nv_bfloat16* src = (term ? base1 : base0) + (size_t)m * KT + kb * 8;
            cp16(sb + O_A + term * A_TERM_B + m * 528 + kb * 16, src);
        }
        CP_COMMIT();
    }

    // B chunk loader: it = offset*4 + chunk
    auto load_b = [&](int it) {
        int ko = it >> 2, c = it & 3, st = it & 1;
        const __nv_bfloat16* wb0 = g_wh + (size_t)ko * CO * KT;
        const __nv_bfloat16* wb1 = g_wl + (size_t)ko * CO * KT;
        uint32_t dstb = sb + O_B + st * B_STAGE_B;
        for (int i = tid; i < 2048; i += 256) {
            int term = i >> 10, rem = i & 1023, n = rem >> 3, kb = rem & 7;
            const __nv_bfloat16* src = (term ? wb1 : wb0) + (size_t)n * KT + c * 64 + kb * 8;
            cp16(dstb + term * B_TERM_B + n * 144 + kb * 16, src);
        }
        CP_COMMIT();
    };
    load_b(0);

    float c[2][8][4];
#pragma unroll
    for (int mt = 0; mt < 2; mt++)
#pragma unroll
        for (int nt = 0; nt < 8; nt++)
#pragma unroll
            for (int e = 0; e < 4; e++) c[mt][nt][e] = 0.f;

    // per-thread ldmatrix base addresses (canonical x4 pattern)
    const int lrow = lane & 15, lcb = lane >> 4;
    const uint32_t aBase = sb + O_A + (wm * 32 + lrow) * 528 + lcb * 16;
    const uint32_t bBase = sb + O_B + (wn * 64 + lrow) * 144 + lcb * 16;

    for (int it = 0; it < 32; it++) {
        if (it + 1 < 32) { load_b(it + 1); CP_WAIT(1); }
        else             { CP_WAIT(0); }
        __syncthreads();

        const int st = it & 1, cch = it & 3, ko = it >> 2;
        const uint32_t bStage = bBase + st * B_STAGE_B;

#pragma unroll
        for (int term = 0; term < 3; term++) {
            const uint32_t aT = aBase + (term == 2 ? A_TERM_B : 0);
            const uint32_t bT = bStage + (term == 1 ? B_TERM_B : 0);
#pragma unroll
            for (int ks = 0; ks < 4; ks++) {
                uint32_t a0[4], a1[4];
                const uint32_t akoff = (uint32_t)((cch * 8 + ks * 2) * 16);
                ldsm4(a0, aT + akoff);
                ldsm4(a1, aT + 16 * 528 + akoff);
                uint32_t bfr[8][2];
#pragma unroll
                for (int p = 0; p < 4; p++) {
                    uint32_t r[4];
                    ldsm4(r, bT + p * 16 * 144 + ks * 32);
                    bfr[2 * p][0] = r[0]; bfr[2 * p][1] = r[2];
                    bfr[2 * p + 1][0] = r[1]; bfr[2 * p + 1][1] = r[3];
                }
#pragma unroll
                for (int nt = 0; nt < 8; nt++) {
                    mma16816(c[0][nt], a0, bfr[nt]);
                    mma16816(c[1][nt], a1, bfr[nt]);
                }
            }
        }
        __syncthreads();

        if (cch == 3) {  // offset ko complete -> epilogue
            const size_t rbase = (size_t)ko * MT + (size_t)bx * BM + wm * 32 + (lane >> 2);
            const int colb = wn * 64 + (lane & 3) * 2;
#pragma unroll
            for (int mt = 0; mt < 2; mt++) {
#pragma unroll
                for (int nt = 0; nt < 8; nt++) {
                    float2 v0 = make_float2(c[mt][nt][0], c[mt][nt][1]);
                    float2 v1 = make_float2(c[mt][nt][2], c[mt][nt][3]);
                    float* p0 = out + (rbase + mt * 16) * CO + colb + nt * 8;
                    *(float2*)p0 = v0;
                    *(float2*)(p0 + 8 * CO) = v1;
                }
            }
            // deterministic per-channel partial stats
#pragma unroll
            for (int nt = 0; nt < 8; nt++) {
#pragma unroll
                for (int cp = 0; cp < 2; cp++) {
                    float s = c[0][nt][cp] + c[0][nt][cp + 2] +
                              c[1][nt][cp] + c[1][nt][cp + 2];
                    float q = c[0][nt][cp] * c[0][nt][cp] + c[0][nt][cp + 2] * c[0][nt][cp + 2] +
                              c[1][nt][cp] * c[1][nt][cp] + c[1][nt][cp + 2] * c[1][nt][cp + 2];
                    s += __shfl_down_sync(0xffffffffu, s, 16);
                    s += __shfl_down_sync(0xffffffffu, s, 8);
                    s += __shfl_down_sync(0xffffffffu, s, 4);
                    q += __shfl_down_sync(0xffffffffu, q, 16);
                    q += __shfl_down_sync(0xffffffffu, q, 8);
                    q += __shfl_down_sync(0xffffffffu, q, 4);
                    if (lane < 4) {
                        int ch = wn * 64 + nt * 8 + lane * 2 + cp;
                        accS[wm * CO + ch] += s;
                        accQ[wm * CO + ch] += q;
                    }
                }
            }
#pragma unroll
            for (int mt = 0; mt < 2; mt++)
#pragma unroll
                for (int nt = 0; nt < 8; nt++)
#pragma unroll
                    for (int e = 0; e < 4; e++) c[mt][nt][e] = 0.f;
        }
    }

    __syncthreads();
    if (tid < CO) {
        float s = accS[tid] + accS[CO + tid] + accS[2 * CO + tid] + accS[3 * CO + tid];
        float q = accQ[tid] + accQ[CO + tid] + accQ[2 * CO + tid] + accQ[3 * CO + tid];
        g_psum[(size_t)bx * CO + tid] = s;
        g_psq [(size_t)bx * CO + tid] = q;
    }
}

// ============================================================================
// stats + BN/ReLU
// ============================================================================
__global__ __launch_bounds__(256) void stats_k(const float* __restrict__ gamma,
                                               const float* __restrict__ beta)
{
    const int d = blockIdx.x;
    __shared__ float ss[256], sq[256];
    float s = 0.f, q = 0.f;
    for (int i = threadIdx.x; i < MTILES; i += 256) {
        s += g_psum[(size_t)i * CO + d];
        q += g_psq [(size_t)i * CO + d];
    }
    ss[threadIdx.x] = s; sq[threadIdx.x] = q;
    __syncthreads();
    for (int st = 128; st > 0; st >>= 1) {
        if (threadIdx.x < st) {
            ss[threadIdx.x] += ss[threadIdx.x + st];
            sq[threadIdx.x] += sq[threadIdx.x + st];
        }
        __syncthreads();
    }
    if (threadIdx.x == 0) {
        const float inv = 1.f / (float)((size_t)NOFF * MT);
        float mean = ss[0] * inv;
        float var  = sq[0] * inv - mean * mean;
        float sc   = gamma[d] * rsqrtf(var + 1e-5f);
        g_scale[d] = sc;
        g_bias[d]  = beta[d] - mean * sc;
    }
}

__global__ __launch_bounds__(256) void bn_relu(float* __restrict__ out)
{
    __shared__ float sc[CO], bi[CO];
    if (threadIdx.x < CO) {
        sc[threadIdx.x] = g_scale[threadIdx.x];
        bi[threadIdx.x] = g_bias[threadIdx.x];
    }
    __syncthreads();
    const size_t idx = (size_t)blockIdx.x * blockDim.x + threadIdx.x;  // float4 idx
    const int d0 = (int)((idx * 4) & (CO - 1));
    float4 v = ((float4*)out)[idx];
    v.x = fmaxf(fmaf(v.x, sc[d0 + 0], bi[d0 + 0]), 0.f);
    v.y = fmaxf(fmaf(v.y, sc[d0 + 1], bi[d0 + 1]), 0.f);
    v.z = fmaxf(fmaf(v.z, sc[d0 + 2], bi[d0 + 2]), 0.f);
    v.w = fmaxf(fmaf(v.w, sc[d0 + 3], bi[d0 + 3]), 0.f);
    ((float4*)out)[idx] = v;
}

// ============================================================================
extern "C" void kernel_launch(void* const* d_in, const int* in_sizes, int n_in,
                              void* d_out, int out_size)
{
    const float* x     = (const float*)d_in[0];   // [65536,256]
    const float* W     = (const float*)d_in[1];   // [8,256,128]
    const float* gamma = (const float*)d_in[2];
    const float* beta  = (const float*)d_in[3];
    float* out = (float*)d_out;

    cudaFuncSetAttribute(gemm_mma, cudaFuncAttributeMaxDynamicSharedMemorySize, SMEM_BYTES);

    convert_x<<<8192, 256>>>(x);
    convert_w<<<NOFF * CO, 256>>>(W);
    gemm_mma<<<MTILES, 256, SMEM_BYTES>>>(out);
    stats_k<<<CO, 256>>>(gamma, beta);
    const size_t n4 = (size_t)NOFF * MT * CO / 4;
    bn_relu<<<(unsigned)(n4 / 256), 256>>>(out);
}

// round 4
// speedup vs baseline: 3.2994x; 1.9195x over previous
#include <cuda_runtime.h>
#include <cuda_fp16.h>
#include <cstdint>

// ============================================================================
// Upsample: out = stack_k(x @ W[k]) [8*65536,128] -> BN(train stats) -> ReLU
// fp16 single-term mma.sync GEMM; BN stats computed ANALYTICALLY before the
// GEMM (mean from colsum(x)@W, E[out^2] from w^T (x^T x) w), so BN+ReLU fuses
// into the GEMM epilogue and the 536MB second pass disappears.
// ============================================================================

#define MT      65536
#define KT      256
#define CO      128
#define NOFF    8
#define BM      128
#define MTILES  512
#define GSPLIT  128           // k-splits for Gram

// ---- device scratch ----
__device__ __align__(16) __half g_xh[(size_t)MT * KT];        // row-major
__device__ __align__(16) __half g_xt[(size_t)KT * MT];        // transposed [chan][row]
__device__ __align__(16) __half g_wh[NOFF * CO * KT];         // [k][n][kk] k-contig
__device__ float g_gp[(size_t)GSPLIT * KT * KT];              // Gram partials
__device__ float g_G [KT * KT];
__device__ float g_cs[KT];
__device__ float g_scale[CO];
__device__ float g_bias [CO];

// ---- PTX helpers ----
__device__ __forceinline__ uint32_t smem_u32(const void* p) {
    uint32_t a;
    asm("{ .reg .u64 t; cvta.to.shared.u64 t, %1; cvt.u32.u64 %0, t; }" : "=r"(a) : "l"(p));
    return a;
}
__device__ __forceinline__ void cp16(uint32_t dst, const void* src) {
    asm volatile("cp.async.cg.shared.global [%0], [%1], 16;" :: "r"(dst), "l"(src) : "memory");
}
#define CP_COMMIT() asm volatile("cp.async.commit_group;" ::: "memory")
#define CP_WAIT(n)  asm volatile("cp.async.wait_group %0;" :: "n"(n) : "memory")

__device__ __forceinline__ void ldsm4(uint32_t r[4], uint32_t a) {
    asm volatile("ldmatrix.sync.aligned.m8n8.x4.shared.b16 {%0,%1,%2,%3}, [%4];"
                 : "=r"(r[0]), "=r"(r[1]), "=r"(r[2]), "=r"(r[3]) : "r"(a));
}
__device__ __forceinline__ void mma16816(float d[4], const uint32_t a[4], const uint32_t b[2]) {
    asm volatile(
        "mma.sync.aligned.m16n8k16.row.col.f32.f16.f16.f32 "
        "{%0,%1,%2,%3}, {%4,%5,%6,%7}, {%8,%9}, {%0,%1,%2,%3};"
        : "+f"(d[0]), "+f"(d[1]), "+f"(d[2]), "+f"(d[3])
        : "r"(a[0]), "r"(a[1]), "r"(a[2]), "r"(a[3]), "r"(b[0]), "r"(b[1]));
}

// ============================================================================
// prep: x -> fp16 (row-major + transposed), W -> fp16 k-contig
// ============================================================================
__global__ __launch_bounds__(256) void convert_x(const float* __restrict__ x) {
    __shared__ __half tile[32][33];
    const int tx = threadIdx.x & 31, ty = threadIdx.x >> 5;
    const int r0 = blockIdx.x * 32, c0 = blockIdx.y * 32;
#pragma unroll
    for (int i = 0; i < 4; i++) {
        int r = ty + i * 8;
        float v = x[(size_t)(r0 + r) * KT + c0 + tx];
        __half h = __float2half(v);
        tile[r][tx] = h;
        g_xh[(size_t)(r0 + r) * KT + c0 + tx] = h;
    }
    __syncthreads();
#pragma unroll
    for (int i = 0; i < 4; i++) {
        int c = ty + i * 8;
        g_xt[(size_t)(c0 + c) * MT + r0 + tx] = tile[tx][c];
    }
}

__global__ __launch_bounds__(256) void convert_w(const float* __restrict__ W) {
    int b = blockIdx.x;              // k*128 + n
    int k = b >> 7, n = b & 127;
    int kk = threadIdx.x;
    g_wh[(size_t)b * KT + kk] = __float2half(W[((size_t)(k * KT + kk)) * CO + n]);
}

// ============================================================================
// colsum(x) per channel (deterministic)
// ============================================================================
__global__ __launch_bounds__(256) void colsum_k() {
    const int ch = blockIdx.x, t = threadIdx.x;
    const uint4* p = (const uint4*)(g_xt + (size_t)ch * MT + (size_t)t * 256);
    float s = 0.f;
#pragma unroll 4
    for (int i = 0; i < 32; i++) {
        uint4 u = p[i];
        const __half2* h2 = (const __half2*)&u;
#pragma unroll
        for (int j = 0; j < 4; j++) { float2 f = __half22float2(h2[j]); s += f.x + f.y; }
    }
    __shared__ float sm[256];
    sm[t] = s; __syncthreads();
    for (int st = 128; st > 0; st >>= 1) {
        if (t < st) sm[t] += sm[t + st];
        __syncthreads();
    }
    if (t == 0) g_cs[ch] = sm[0];
}

// ============================================================================
// Gram partials: G_part[cta] = X[cta slice]^T X[cta slice], fp16 mma
// grid (GSPLIT, 2): y = j-half (128 output cols each). 256 thr, warps 4x2,
// warp tile 64x64.
// ============================================================================
#define GR_STAGE 36864      // 256 rows x 72 halves x 2B
__global__ __launch_bounds__(256, 1) void gram_k()
{
    extern __shared__ char smem[];
    const uint32_t sb = smem_u32(smem);
    const int tid = threadIdx.x, lane = tid & 31, w = tid >> 5;
    const int wm = w & 3, wn = w >> 2;          // 4 x 2
    const int cta = blockIdx.x, jh = blockIdx.y;
    const size_t kbase = (size_t)cta * 512;

    auto load_t = [&](int ch) {
        uint32_t dst = sb + (ch & 1) * GR_STAGE;
        size_t k0 = kbase + ch * 64;
        for (int i = tid; i < 2048; i += 256) {
            int n = i >> 3, kb = i & 7;
            cp16(dst + n * 144 + kb * 16, g_xt + (size_t)n * MT + k0 + kb * 8);
        }
        CP_COMMIT();
    };
    load_t(0);

    float c[4][8][4];
#pragma unroll
    for (int a = 0; a < 4; a++)
#pragma unroll
        for (int b = 0; b < 8; b++)
#pragma unroll
            for (int e = 0; e < 4; e++) c[a][b][e] = 0.f;

    const int lrow = lane & 15, lcb = lane >> 4;
    const uint32_t aB = sb + (wm * 64 + lrow) * 144 + lcb * 16;
    const uint32_t bB = sb + (jh * 128 + wn * 64 + lrow) * 144 + lcb * 16;

    for (int ch = 0; ch < 8; ch++) {
        if (ch + 1 < 8) { load_t(ch + 1); CP_WAIT(1); }
        else            { CP_WAIT(0); }
        __syncthreads();
        const uint32_t off = (ch & 1) * GR_STAGE;
#pragma unroll
        for (int ks = 0; ks < 4; ks++) {
            uint32_t af[4][4];
#pragma unroll
            for (int mf = 0; mf < 4; mf++) ldsm4(af[mf], aB + off + mf * 16 * 144 + ks * 32);
            uint32_t bf[8][2];
#pragma unroll
            for (int p = 0; p < 4; p++) {
                uint32_t r[4];
                ldsm4(r, bB + off + p * 16 * 144 + ks * 32);
                bf[2 * p][0] = r[0]; bf[2 * p][1] = r[2];
                bf[2 * p + 1][0] = r[1]; bf[2 * p + 1][1] = r[3];
            }
#pragma unroll
            for (int mf = 0; mf < 4; mf++)
#pragma unroll
                for (int nt = 0; nt < 8; nt++) mma16816(c[mf][nt], af[mf], bf[nt]);
        }
        __syncthreads();
    }

    float* dst = g_gp + (size_t)cta * (KT * KT);
#pragma unroll
    for (int mf = 0; mf < 4; mf++)
#pragma unroll
        for (int nt = 0; nt < 8; nt++) {
            int i0 = wm * 64 + mf * 16 + (lane >> 2);
            int j0 = jh * 128 + wn * 64 + nt * 8 + (lane & 3) * 2;
            *(float2*)(dst + (size_t)i0 * KT + j0) = make_float2(c[mf][nt][0], c[mf][nt][1]);
            *(float2*)(dst + (size_t)(i0 + 8) * KT + j0) = make_float2(c[mf][nt][2], c[mf][nt][3]);
        }
}

__global__ __launch_bounds__(256) void gram_reduce() {
    const int i = blockIdx.x, j = threadIdx.x;
    float s = 0.f;
    const float* p = g_gp + (size_t)i * KT + j;
    for (int q = 0; q < GSPLIT; q++) s += p[(size_t)q * (KT * KT)];
    g_G[i * KT + j] = s;
}

// ============================================================================
// stats: per output channel d, over ALL 8 offsets:
//   mean = cs . (sum_k W_k[:,d]) / (8N);  E[o^2] = sum_k w^T G w / (8N)
// ============================================================================
__global__ __launch_bounds__(256) void stats_k(const float* __restrict__ W,
                                               const float* __restrict__ gamma,
                                               const float* __restrict__ beta)
{
    const int d = blockIdx.x, j = threadIdx.x;
    __shared__ float Ws[NOFF][KT];
    __shared__ float red[256];
#pragma unroll
    for (int k = 0; k < NOFF; k++)
        Ws[k][j] = W[((size_t)k * KT + j) * CO + d];
    __syncthreads();

    float inner[NOFF];
#pragma unroll
    for (int k = 0; k < NOFF; k++) inner[k] = 0.f;
    for (int i = 0; i < KT; i++) {
        float g = g_G[i * KT + j];
#pragma unroll
        for (int k = 0; k < NOFF; k++) inner[k] = fmaf(g, Ws[k][i], inner[k]);
    }
    float qj = 0.f, mj = 0.f;
    const float csj = g_cs[j];
#pragma unroll
    for (int k = 0; k < NOFF; k++) {
        qj = fmaf(inner[k], Ws[k][j], qj);
        mj = fmaf(csj, Ws[k][j], mj);
    }
    red[j] = qj; __syncthreads();
    for (int st = 128; st > 0; st >>= 1) { if (j < st) red[j] += red[j + st]; __syncthreads(); }
    float qtot = red[0]; __syncthreads();
    red[j] = mj; __syncthreads();
    for (int st = 128; st > 0; st >>= 1) { if (j < st) red[j] += red[j + st]; __syncthreads(); }
    if (j == 0) {
        const float invN = 1.f / (float)((size_t)NOFF * MT);
        float mean = red[0] * invN;
        float var  = qtot * invN - mean * mean;
        float sc   = gamma[d] * rsqrtf(var + 1e-5f);
        g_scale[d] = sc;
        g_bias[d]  = beta[d] - mean * sc;
    }
}

// ============================================================================
// main GEMM (fp16, single term) with fused BN+ReLU epilogue
// ============================================================================
#define O_A    0
#define A_BYTES 67584                  // 128 * 264 halves
#define O_B    A_BYTES
#define B_STAGE 18432                  // 128 * 72 halves
#define O_SC   (O_B + 2 * B_STAGE)     // 104448
#define SMEM_G (O_SC + 1024)           // + sc[128], bi[128]

__global__ __launch_bounds__(256, 2) void gemm_mma(float* __restrict__ out)
{
    extern __shared__ char smem[];
    const uint32_t sb = smem_u32(smem);
    const int tid = threadIdx.x, lane = tid & 31, w = tid >> 5;
    const int wm = w & 3, wn = w >> 2;          // 4 x 2 warp grid
    const int bx = blockIdx.x;

    float* scs = (float*)(smem + O_SC);
    float* bis = scs + CO;
    if (tid < CO) { scs[tid] = g_scale[tid]; bis[tid] = g_bias[tid]; }

    // A tile via cp.async: 128 rows x 32 x 16B
    {
        const __half* base = g_xh + (size_t)bx * BM * KT;
        for (int i = tid; i < 4096; i += 256) {
            int m = i >> 5, kb = i & 31;
            cp16(sb + O_A + m * 528 + kb * 16, base + (size_t)m * KT + kb * 8);
        }
        CP_COMMIT();
    }

    auto load_b = [&](int it) {
        int ko = it >> 2, c = it & 3, st = it & 1;
        const __half* wb = g_wh + (size_t)ko * CO * KT;
        uint32_t dstb = sb + O_B + st * B_STAGE;
        for (int i = tid; i < 1024; i += 256) {
            int n = i >> 3, kb = i & 7;
            cp16(dstb + n * 144 + kb * 16, wb + (size_t)n * KT + c * 64 + kb * 8);
        }
        CP_COMMIT();
    };
    load_b(0);

    float c[2][8][4];
#pragma unroll
    for (int mt = 0; mt < 2; mt++)
#pragma unroll
        for (int nt = 0; nt < 8; nt++)
#pragma unroll
            for (int e = 0; e < 4; e++) c[mt][nt][e] = 0.f;

    const int lrow = lane & 15, lcb = lane >> 4;
    const uint32_t aBase = sb + O_A + (wm * 32 + lrow) * 528 + lcb * 16;
    const uint32_t bBase = sb + O_B + (wn * 64 + lrow) * 144 + lcb * 16;

    for (int it = 0; it < 32; it++) {
        if (it + 1 < 32) { load_b(it + 1); CP_WAIT(1); }
        else             { CP_WAIT(0); }
        __syncthreads();

        const int st = it & 1, cch = it & 3, ko = it >> 2;
        const uint32_t bStage = bBase + st * B_STAGE;

#pragma unroll
        for (int ks = 0; ks < 4; ks++) {
            uint32_t a0[4], a1[4];
            const uint32_t akoff = (uint32_t)((cch * 8 + ks * 2) * 16);
            ldsm4(a0, aBase + akoff);
            ldsm4(a1, aBase + 16 * 528 + akoff);
            uint32_t bfr[8][2];
#pragma unroll
            for (int p = 0; p < 4; p++) {
                uint32_t r[4];
                ldsm4(r, bStage + p * 16 * 144 + ks * 32);
                bfr[2 * p][0] = r[0]; bfr[2 * p][1] = r[2];
                bfr[2 * p + 1][0] = r[1]; bfr[2 * p + 1][1] = r[3];
            }
#pragma unroll
            for (int nt = 0; nt < 8; nt++) {
                mma16816(c[0][nt], a0, bfr[nt]);
                mma16816(c[1][nt], a1, bfr[nt]);
            }
        }
        __syncthreads();

        if (cch == 3) {  // offset ko complete: fused BN + ReLU epilogue
            const size_t rbase = (size_t)ko * MT + (size_t)bx * BM + wm * 32 + (lane >> 2);
            const int colb = wn * 64 + (lane & 3) * 2;
#pragma unroll
            for (int nt = 0; nt < 8; nt++) {
                const int ch0 = colb + nt * 8;
                const float s0 = scs[ch0], s1 = scs[ch0 + 1];
                const float b0 = bis[ch0], b1 = bis[ch0 + 1];
#pragma unroll
                for (int mt = 0; mt < 2; mt++) {
                    float y0 = fmaxf(fmaf(c[mt][nt][0], s0, b0), 0.f);
                    float y1 = fmaxf(fmaf(c[mt][nt][1], s1, b1), 0.f);
                    float y2 = fmaxf(fmaf(c[mt][nt][2], s0, b0), 0.f);
                    float y3 = fmaxf(fmaf(c[mt][nt][3], s1, b1), 0.f);
                    float* p0 = out + (rbase + mt * 16) * CO + ch0;
                    *(float2*)p0 = make_float2(y0, y1);
                    *(float2*)(p0 + 8 * CO) = make_float2(y2, y3);
                }
            }
#pragma unroll
            for (int mt = 0; mt < 2; mt++)
#pragma unroll
                for (int nt = 0; nt < 8; nt++)
#pragma unroll
                    for (int e = 0; e < 4; e++) c[mt][nt][e] = 0.f;
        }
    }
}

// ============================================================================
extern "C" void kernel_launch(void* const* d_in, const int* in_sizes, int n_in,
                              void* d_out, int out_size)
{
    const float* x     = (const float*)d_in[0];   // [65536,256]
    const float* W     = (const float*)d_in[1];   // [8,256,128]
    const float* gamma = (const float*)d_in[2];
    const float* beta  = (const float*)d_in[3];
    float* out = (float*)d_out;

    cudaFuncSetAttribute(gram_k,   cudaFuncAttributeMaxDynamicSharedMemorySize, 2 * GR_STAGE);
    cudaFuncSetAttribute(gemm_mma, cudaFuncAttributeMaxDynamicSharedMemorySize, SMEM_G);

    dim3 cgrid(MT / 32, KT / 32);
    convert_x<<<cgrid, 256>>>(x);
    convert_w<<<NOFF * CO, 256>>>(W);
    colsum_k<<<KT, 256>>>();
    dim3 ggrid(GSPLIT, 2);
    gram_k<<<ggrid, 256, 2 * GR_STAGE>>>();
    gram_reduce<<<KT, 256>>>();
    stats_k<<<CO, 256>>>(W, gamma, beta);
    gemm_mma<<<MTILES, 256, SMEM_G>>>(out);
}

// round 5
// speedup vs baseline: 3.5543x; 1.0773x over previous
#include <cuda_runtime.h>
#include <cuda_fp16.h>
#include <cstdint>

// ============================================================================
// Upsample: out = stack_k(x @ W[k]) [8*65536,128] -> BN(train stats) -> ReLU
// fp16 mma.sync GEMM with analytic BN stats (colsum + Gram) and fused
// BN+ReLU epilogue. R5: XOR-swizzled smem, 1-sync pipelines, 2 CTA/SM.
// ============================================================================

#define MT      65536
#define KT      256
#define CO      128
#define NOFF    8
#define BM      128
#define MTILES  512
#define GSPLIT  64            // k-splits for Gram (1024 rows each)

// ---- device scratch ----
__device__ __align__(16) __half g_xh[(size_t)MT * KT];        // row-major
__device__ __align__(16) __half g_xt[(size_t)KT * MT];        // transposed
__device__ __align__(16) __half g_wh[NOFF * CO * KT];         // [k][n][kk]
__device__ float g_gp[(size_t)GSPLIT * KT * KT];              // Gram partials
__device__ float g_G [KT * KT];
__device__ float g_cs[KT];
__device__ float g_scale[CO];
__device__ float g_bias [CO];

// ---- PTX helpers ----
__device__ __forceinline__ uint32_t smem_u32(const void* p) {
    uint32_t a;
    asm("{ .reg .u64 t; cvta.to.shared.u64 t, %1; cvt.u32.u64 %0, t; }" : "=r"(a) : "l"(p));
    return a;
}
__device__ __forceinline__ void cp16(uint32_t dst, const void* src) {
    asm volatile("cp.async.cg.shared.global [%0], [%1], 16;" :: "r"(dst), "l"(src) : "memory");
}
#define CP_COMMIT() asm volatile("cp.async.commit_group;" ::: "memory")
#define CP_WAIT(n)  asm volatile("cp.async.wait_group %0;" :: "n"(n) : "memory")

__device__ __forceinline__ void ldsm4(uint32_t r[4], uint32_t a) {
    asm volatile("ldmatrix.sync.aligned.m8n8.x4.shared.b16 {%0,%1,%2,%3}, [%4];"
                 : "=r"(r[0]), "=r"(r[1]), "=r"(r[2]), "=r"(r[3]) : "r"(a));
}
__device__ __forceinline__ void mma16816(float d[4], const uint32_t a[4], const uint32_t b[2]) {
    asm volatile(
        "mma.sync.aligned.m16n8k16.row.col.f32.f16.f16.f32 "
        "{%0,%1,%2,%3}, {%4,%5,%6,%7}, {%8,%9}, {%0,%1,%2,%3};"
        : "+f"(d[0]), "+f"(d[1]), "+f"(d[2]), "+f"(d[3])
        : "r"(a[0]), "r"(a[1]), "r"(a[2]), "r"(a[3]), "r"(b[0]), "r"(b[1]));
}

// ============================================================================
// prep: x -> fp16 row-major + transposed (vectorized), W -> fp16 k-contig
// ============================================================================
__global__ __launch_bounds__(256) void convert_x(const float* __restrict__ x) {
    __shared__ __half tile[64 * 65];          // stride 65: conflict-free strided
    const int tid = threadIdx.x;
    const int r0 = blockIdx.x * 64, c0 = blockIdx.y * 64;
#pragma unroll
    for (int h = 0; h < 2; h++) {
        int rl = h * 32 + (tid >> 3), cl = (tid & 7) * 8;
        const float* src = x + (size_t)(r0 + rl) * KT + c0 + cl;
        float4 f0 = *(const float4*)src;
        float4 f1 = *(const float4*)(src + 4);
        float v[8] = {f0.x, f0.y, f0.z, f0.w, f1.x, f1.y, f1.z, f1.w};
        __half hh[8];
#pragma unroll
        for (int j = 0; j < 8; j++) hh[j] = __float2half(v[j]);
        *(uint4*)(g_xh + (size_t)(r0 + rl) * KT + c0 + cl) = *(uint4*)hh;
#pragma unroll
        for (int j = 0; j < 8; j++) tile[rl * 65 + cl + j] = hh[j];
    }
    __syncthreads();
#pragma unroll
    for (int h = 0; h < 2; h++) {
        int cl = h * 32 + (tid >> 3), rl = (tid & 7) * 8;
        __half t[8];
#pragma unroll
        for (int j = 0; j < 8; j++) t[j] = tile[(rl + j) * 65 + cl];
        *(uint4*)(g_xt + (size_t)(c0 + cl) * MT + r0 + rl) = *(uint4*)t;
    }
}

__global__ __launch_bounds__(256) void convert_w(const float* __restrict__ W) {
    int b = blockIdx.x;              // k*128 + n
    int k = b >> 7, n = b & 127;
    int kk = threadIdx.x;
    g_wh[(size_t)b * KT + kk] = __float2half(W[((size_t)(k * KT + kk)) * CO + n]);
}

// ============================================================================
// colsum(x) per channel (deterministic)
// ============================================================================
__global__ __launch_bounds__(256) void colsum_k() {
    const int ch = blockIdx.x, t = threadIdx.x;
    const uint4* p = (const uint4*)(g_xt + (size_t)ch * MT + (size_t)t * 256);
    float s = 0.f;
#pragma unroll 4
    for (int i = 0; i < 32; i++) {
        uint4 u = p[i];
        const __half2* h2 = (const __half2*)&u;
#pragma unroll
        for (int j = 0; j < 4; j++) { float2 f = __half22float2(h2[j]); s += f.x + f.y; }
    }
    __shared__ float sm[256];
    sm[t] = s; __syncthreads();
    for (int st = 128; st > 0; st >>= 1) {
        if (t < st) sm[t] += sm[t + st];
        __syncthreads();
    }
    if (t == 0) g_cs[ch] = sm[0];
}

// ============================================================================
// Gram partials: grid (GSPLIT, 4). Each CTA: 1024 rows of X, 64 output cols.
// 2-stage XOR-swizzled pipeline, 1 sync/iter. Warps 4x2, warp tile 64x32.
// ============================================================================
#define GR_STAGE 32768      // 256 ch x 128B (XOR swizzled, 64 halves/row)
__global__ __launch_bounds__(256, 2) void gram_k()
{
    extern __shared__ char smem[];
    const uint32_t sb = smem_u32(smem);
    const int tid = threadIdx.x, lane = tid & 31, w = tid >> 5;
    const int wm = w & 3, wn = w >> 2;          // 4 x 2
    const int cta = blockIdx.x, jh = blockIdx.y;
    const size_t kbase = (size_t)cta * 1024;

    auto load_t = [&](int ch) {
        uint32_t dst = sb + (ch & 1) * GR_STAGE;
        size_t k0 = kbase + (size_t)ch * 64;
        for (int i = tid; i < 2048; i += 256) {
            int n = i >> 3, kb = i & 7;
            cp16(dst + n * 128 + (uint32_t)((kb ^ (n & 7)) << 4),
                 g_xt + (size_t)n * MT + k0 + kb * 8);
        }
        CP_COMMIT();
    };
    load_t(0);

    float c[4][4][4];
#pragma unroll
    for (int a = 0; a < 4; a++)
#pragma unroll
        for (int b = 0; b < 4; b++)
#pragma unroll
            for (int e = 0; e < 4; e++) c[a][b][e] = 0.f;

    const int lrow = lane & 15, lcb = lane >> 4, xm = lane & 7;
    const uint32_t aRow = sb + (wm * 64 + lrow) * 128;
    const uint32_t bRow = sb + (jh * 64 + wn * 32 + lrow) * 128;

    for (int ch = 0; ch < 16; ch++) {
        CP_WAIT(0);
        __syncthreads();
        if (ch + 1 < 16) load_t(ch + 1);
        const uint32_t off = (ch & 1) * GR_STAGE;
#pragma unroll
        for (int ks = 0; ks < 4; ks++) {
            const uint32_t u = (uint32_t)(((ks * 2 + lcb) ^ xm) << 4);
            uint32_t af[4][4];
#pragma unroll
            for (int mf = 0; mf < 4; mf++) ldsm4(af[mf], aRow + off + mf * 16 * 128 + u);
            uint32_t bf[4][2];
#pragma unroll
            for (int p = 0; p < 2; p++) {
                uint32_t r[4];
                ldsm4(r, bRow + off + p * 16 * 128 + u);
                bf[2 * p][0] = r[0]; bf[2 * p][1] = r[2];
                bf[2 * p + 1][0] = r[1]; bf[2 * p + 1][1] = r[3];
            }
#pragma unroll
            for (int mf = 0; mf < 4; mf++)
#pragma unroll
                for (int nt = 0; nt < 4; nt++) mma16816(c[mf][nt], af[mf], bf[nt]);
        }
    }

    float* dst = g_gp + (size_t)cta * (KT * KT);
#pragma unroll
    for (int mf = 0; mf < 4; mf++)
#pragma unroll
        for (int nt = 0; nt < 4; nt++) {
            int i0 = wm * 64 + mf * 16 + (lane >> 2);
            int j0 = jh * 64 + wn * 32 + nt * 8 + (lane & 3) * 2;
            *(float2*)(dst + (size_t)i0 * KT + j0) = make_float2(c[mf][nt][0], c[mf][nt][1]);
            *(float2*)(dst + (size_t)(i0 + 8) * KT + j0) = make_float2(c[mf][nt][2], c[mf][nt][3]);
        }
}

__global__ __launch_bounds__(256) void gram_reduce() {
    const int i = blockIdx.x, j = threadIdx.x;
    float s = 0.f;
    const float* p = g_gp + (size_t)i * KT + j;
    for (int q = 0; q < GSPLIT; q++) s += p[(size_t)q * (KT * KT)];
    g_G[i * KT + j] = s;
}

// ============================================================================
// stats: mean = cs.(sum_k W_k[:,d])/(8N); E[o^2] = sum_k w^T G w /(8N)
// ============================================================================
__global__ __launch_bounds__(256) void stats_k(const float* __restrict__ W,
                                               const float* __restrict__ gamma,
                                               const float* __restrict__ beta)
{
    const int d = blockIdx.x, j = threadIdx.x;
    __shared__ float Ws[NOFF][KT];
    __shared__ float red[256];
#pragma unroll
    for (int k = 0; k < NOFF; k++)
        Ws[k][j] = W[((size_t)k * KT + j) * CO + d];
    __syncthreads();

    float inner[NOFF];
#pragma unroll
    for (int k = 0; k < NOFF; k++) inner[k] = 0.f;
    for (int i = 0; i < KT; i++) {
        float g = g_G[i * KT + j];
#pragma unroll
        for (int k = 0; k < NOFF; k++) inner[k] = fmaf(g, Ws[k][i], inner[k]);
    }
    float qj = 0.f, mj = 0.f;
    const float csj = g_cs[j];
#pragma unroll
    for (int k = 0; k < NOFF; k++) {
        qj = fmaf(inner[k], Ws[k][j], qj);
        mj = fmaf(csj, Ws[k][j], mj);
    }
    red[j] = qj; __syncthreads();
    for (int st = 128; st > 0; st >>= 1) { if (j < st) red[j] += red[j + st]; __syncthreads(); }
    float qtot = red[0]; __syncthreads();
    red[j] = mj; __syncthreads();
    for (int st = 128; st > 0; st >>= 1) { if (j < st) red[j] += red[j + st]; __syncthreads(); }
    if (j == 0) {
        const float invN = 1.f / (float)((size_t)NOFF * MT);
        float mean = red[0] * invN;
        float var  = qtot * invN - mean * mean;
        float sc   = gamma[d] * rsqrtf(var + 1e-5f);
        g_scale[d] = sc;
        g_bias[d]  = beta[d] - mean * sc;
    }
}

// ============================================================================
// main GEMM (fp16) with fused BN+ReLU epilogue. XOR-swizzled A (64KB resident)
// + 2-stage B (16KB each); 1 __syncthreads per iteration.
// ============================================================================
#define O_A     0
#define A_BYTES 65536                  // 128 rows x 512B (XOR swizzled)
#define O_B     A_BYTES
#define B_STAGE 16384                  // 128 n x 128B (XOR swizzled)
#define O_SC    (O_B + 2 * B_STAGE)    // 98304
#define SMEM_G  (O_SC + 1024)          // 99328

__global__ __launch_bounds__(256, 2) void gemm_mma(float* __restrict__ out)
{
    extern __shared__ char smem[];
    const uint32_t sb = smem_u32(smem);
    const int tid = threadIdx.x, lane = tid & 31, w = tid >> 5;
    const int wm = w & 3, wn = w >> 2;          // 4 x 2 warp grid
    const int bx = blockIdx.x;

    float* scs = (float*)(smem + O_SC);
    float* bis = scs + CO;
    if (tid < CO) { scs[tid] = g_scale[tid]; bis[tid] = g_bias[tid]; }

    // A tile via cp.async (XOR swizzle): 128 rows x 32 x 16B
    {
        const __half* base = g_xh + (size_t)bx * BM * KT;
        for (int i = tid; i < 4096; i += 256) {
            int m = i >> 5, u = i & 31;
            uint32_t up = (uint32_t)((u & 24) | ((u ^ m) & 7));
            cp16(sb + O_A + m * 512 + (up << 4), base + (size_t)m * KT + u * 8);
        }
        CP_COMMIT();
    }

    auto load_b = [&](int it) {
        int ko = it >> 2, c = it & 3, st = it & 1;
        const __half* wb = g_wh + (size_t)ko * CO * KT;
        uint32_t dstb = sb + O_B + st * B_STAGE;
        for (int i = tid; i < 1024; i += 256) {
            int n = i >> 3, kb = i & 7;
            cp16(dstb + n * 128 + (uint32_t)((kb ^ (n & 7)) << 4),
                 wb + (size_t)n * KT + c * 64 + kb * 8);
        }
        CP_COMMIT();
    };
    load_b(0);

    float c[2][8][4];
#pragma unroll
    for (int mt = 0; mt < 2; mt++)
#pragma unroll
        for (int nt = 0; nt < 8; nt++)
#pragma unroll
            for (int e = 0; e < 4; e++) c[mt][nt][e] = 0.f;

    const int lrow = lane & 15, lcb = lane >> 4, xm = lane & 7;
    const uint32_t aRow  = sb + O_A + (wm * 32 + lrow) * 512;
    const uint32_t aRow2 = aRow + 16 * 512;
    const uint32_t bRow  = sb + O_B + (wn * 64 + lrow) * 128;

    for (int it = 0; it < 32; it++) {
        CP_WAIT(0);
        __syncthreads();
        if (it + 1 < 32) load_b(it + 1);

        const int st = it & 1, cch = it & 3, ko = it >> 2;
        const uint32_t stageOff = (uint32_t)(st * B_STAGE);

#pragma unroll
        for (int ks = 0; ks < 4; ks++) {
            const uint32_t xr = (uint32_t)((ks * 2 + lcb) ^ xm);
            const uint32_t au = (uint32_t)((cch * 8) << 4) + (xr << 4);
            const uint32_t bu = (xr << 4);
            uint32_t a0[4], a1[4];
            ldsm4(a0, aRow + au);
            ldsm4(a1, aRow2 + au);
            uint32_t bfr[8][2];
#pragma unroll
            for (int p = 0; p < 4; p++) {
                uint32_t r[4];
                ldsm4(r, bRow + stageOff + p * 16 * 128 + bu);
                bfr[2 * p][0] = r[0]; bfr[2 * p][1] = r[2];
                bfr[2 * p + 1][0] = r[1]; bfr[2 * p + 1][1] = r[3];
            }
#pragma unroll
            for (int nt = 0; nt < 8; nt++) {
                mma16816(c[0][nt], a0, bfr[nt]);
                mma16816(c[1][nt], a1, bfr[nt]);
            }
        }

        if (cch == 3) {  // offset ko complete: fused BN + ReLU epilogue
            const size_t rbase = (size_t)ko * MT + (size_t)bx * BM + wm * 32 + (lane >> 2);
            const int colb = wn * 64 + (lane & 3) * 2;
#pragma unroll
            for (int nt = 0; nt < 8; nt++) {
                const int ch0 = colb + nt * 8;
                const float s0 = scs[ch0], s1 = scs[ch0 + 1];
                const float b0 = bis[ch0], b1 = bis[ch0 + 1];
#pragma unroll
                for (int mt = 0; mt < 2; mt++) {
                    float y0 = fmaxf(fmaf(c[mt][nt][0], s0, b0), 0.f);
                    float y1 = fmaxf(fmaf(c[mt][nt][1], s1, b1), 0.f);
                    float y2 = fmaxf(fmaf(c[mt][nt][2], s0, b0), 0.f);
                    float y3 = fmaxf(fmaf(c[mt][nt][3], s1, b1), 0.f);
                    float* p0 = out + (rbase + mt * 16) * CO + ch0;
                    *(float2*)p0 = make_float2(y0, y1);
                    *(float2*)(p0 + 8 * CO) = make_float2(y2, y3);
                }
            }
#pragma unroll
            for (int mt = 0; mt < 2; mt++)
#pragma unroll
                for (int nt = 0; nt < 8; nt++)
#pragma unroll
                    for (int e = 0; e < 4; e++) c[mt][nt][e] = 0.f;
        }
    }
}

// ============================================================================
extern "C" void kernel_launch(void* const* d_in, const int* in_sizes, int n_in,
                              void* d_out, int out_size)
{
    const float* x     = (const float*)d_in[0];   // [65536,256]
    const float* W     = (const float*)d_in[1];   // [8,256,128]
    const float* gamma = (const float*)d_in[2];
    const float* beta  = (const float*)d_in[3];
    float* out = (float*)d_out;

    cudaFuncSetAttribute(gram_k,   cudaFuncAttributeMaxDynamicSharedMemorySize, 2 * GR_STAGE);
    cudaFuncSetAttribute(gemm_mma, cudaFuncAttributeMaxDynamicSharedMemorySize, SMEM_G);

    dim3 cgrid(MT / 64, KT / 64);
    convert_x<<<cgrid, 256>>>(x);
    convert_w<<<NOFF * CO, 256>>>(W);
    colsum_k<<<KT, 256>>>();
    dim3 ggrid(GSPLIT, 4);
    gram_k<<<ggrid, 256, 2 * GR_STAGE>>>();
    gram_reduce<<<KT, 256>>>();
    stats_k<<<CO, 256>>>(W, gamma, beta);
    gemm_mma<<<MTILES, 256, SMEM_G>>>(out);
}